// round 16
// baseline (speedup 1.0000x reference)
#include <cuda_runtime.h>
#include <cstdint>
#include <cstddef>

#define T_STEPS 2048
#define BATCH   64
#define HID     256
#define NLAYER  2
#define MROWS   (T_STEPS * BATCH)       // 131072

// h_s smem: per buffer 8 slices (32 j each) of 8 b'; slice stride 260
// floats -> dot LDS.128: quads 4*ks mod 32 distinct -> 1 phase.
#define HS_SL   260
#define HS_BUF  (8 * HS_SL)             // 2080 floats per buffer

// ---------------- scratch (static device memory; no allocation APIs) -------
__device__ float g_pre[(size_t)NLAYER * MROWS * 1024];      // 1 GiB

// ---------------- packed fp32x2 helpers ------------------------------------
__device__ __forceinline__ unsigned long long pack2(float x, float y) {
    unsigned long long r;
    asm("mov.b64 %0, {%1, %2};" : "=l"(r) : "f"(x), "f"(y));
    return r;
}
__device__ __forceinline__ void unpack2(unsigned long long v, float& x, float& y) {
    asm("mov.b64 {%0, %1}, %2;" : "=f"(x), "=f"(y) : "l"(v));
}
__device__ __forceinline__ void fma2(unsigned long long& d, unsigned long long a,
                                     unsigned long long b) {
    asm("fma.rn.f32x2 %0, %1, %2, %0;" : "+l"(d) : "l"(a), "l"(b));
}
__device__ __forceinline__ unsigned long long add2(unsigned long long a,
                                                   unsigned long long b) {
    unsigned long long r;
    asm("add.rn.f32x2 %0, %1, %2;" : "=l"(r) : "l"(a), "l"(b));
    return r;
}

// MUFU-path activations
__device__ __forceinline__ float fast_sigmoid(float x) {
    float e, r;
    asm("ex2.approx.f32 %0, %1;" : "=f"(e) : "f"(-1.4426950408889634f * x));
    asm("rcp.approx.f32 %0, %1;" : "=f"(r) : "f"(1.0f + e));
    return r;
}
__device__ __forceinline__ float fast_tanh(float x) {
    float e, r;
    asm("ex2.approx.f32 %0, %1;" : "=f"(e) : "f"(2.8853900817779268f * x));
    asm("rcp.approx.f32 %0, %1;" : "=f"(r) : "f"(1.0f + e));
    return 1.0f - 2.0f * r;
}

__device__ __forceinline__ uint32_t smem_u32(const void* p) {
    uint32_t a;
    asm("{ .reg .u64 t; cvta.to.shared.u64 t, %1; cvt.u32.u64 %0, t; }"
        : "=r"(a) : "l"(p));
    return a;
}
__device__ __forceinline__ uint32_t mapa_rank(uint32_t local, int rank) {
    uint32_t r;
    asm("mapa.shared::cluster.u32 %0, %1, %2;" : "=r"(r) : "r"(local), "r"(rank));
    return r;
}

// ---------------- kernel 1: pre[l,t,b,:] = x[t,b,:] @ Wx[l] + b[l] ---------
__global__ __launch_bounds__(256, 2) void k_pre(const float* __restrict__ x,
                                                const float* __restrict__ W,
                                                const float* __restrict__ bias) {
    __shared__ __align__(16) float As[32 * 132];
    __shared__ __align__(16) float Bs[32 * 128];

    int bid  = blockIdx.x;
    int l    = bid >> 13;
    int rem  = bid & 8191;
    int mt   = rem >> 3;
    int nt   = rem & 7;
    int row0 = mt << 7;
    int col0 = nt << 7;
    int tid  = threadIdx.x;
    int tm   = tid >> 4;
    int tn   = tid & 15;

    const float* Wl = W + (size_t)l * 512 * 1024;

    unsigned long long acc[8][4];
#pragma unroll
    for (int i = 0; i < 8; i++)
#pragma unroll
        for (int j = 0; j < 4; j++) acc[i][j] = 0ULL;

    for (int kc = 0; kc < 256; kc += 32) {
#pragma unroll
        for (int i = 0; i < 4; i++) {
            int aidx = tid + i * 256;
            int m    = aidx >> 3;
            int k4   = (aidx & 7) << 2;
            float4 v = *(const float4*)&x[(size_t)(row0 + m) * 256 + kc + k4];
            As[(k4 + 0) * 132 + m] = v.x;
            As[(k4 + 1) * 132 + m] = v.y;
            As[(k4 + 2) * 132 + m] = v.z;
            As[(k4 + 3) * 132 + m] = v.w;
        }
#pragma unroll
        for (int i = 0; i < 4; i++) {
            int kk = (tid >> 5) + i * 8;
            int n4 = (tid & 31) << 2;
            *(float4*)&Bs[kk * 128 + n4] =
                *(const float4*)&Wl[(size_t)(kc + kk) * 1024 + col0 + n4];
        }
        __syncthreads();

#pragma unroll
        for (int k = 0; k < 32; k++) {
            float4 a0 = *(const float4*)&As[k * 132 + tm * 8];
            float4 a1 = *(const float4*)&As[k * 132 + tm * 8 + 4];
            ulonglong2 bb01 = *(const ulonglong2*)&Bs[k * 128 + tn * 8];
            ulonglong2 bb23 = *(const ulonglong2*)&Bs[k * 128 + tn * 8 + 4];
            float av[8] = {a0.x, a0.y, a0.z, a0.w, a1.x, a1.y, a1.z, a1.w};
#pragma unroll
            for (int i = 0; i < 8; i++) {
                unsigned long long a2 = pack2(av[i], av[i]);
                fma2(acc[i][0], a2, bb01.x);
                fma2(acc[i][1], a2, bb01.y);
                fma2(acc[i][2], a2, bb23.x);
                fma2(acc[i][3], a2, bb23.y);
            }
        }
        __syncthreads();
    }

    float bv[8];
#pragma unroll
    for (int j = 0; j < 8; j++) bv[j] = bias[l * 1024 + col0 + tn * 8 + j];
#pragma unroll
    for (int i = 0; i < 8; i++) {
        float o[8];
#pragma unroll
        for (int j = 0; j < 4; j++) unpack2(acc[i][j], o[2 * j], o[2 * j + 1]);
#pragma unroll
        for (int j = 0; j < 8; j++) o[j] += bv[j];
        size_t base = ((size_t)l * MROWS + row0 + tm * 8 + i) * 1024 + col0 + tn * 8;
        __stcs((float4*)&g_pre[base],     make_float4(o[0], o[1], o[2], o[3]));
        __stcs((float4*)&g_pre[base + 4], make_float4(o[4], o[5], o[6], o[7]));
    }
}

// ---------------- kernel 2: persistent recurrence (8-CTA clusters) ----------
// 128 CTAs = 16 clusters of 8. Cluster = (layer, b-octet); rank = hR
// (32 hcols). 256 threads = 8 warps. warp o; lane = ks(3b)|hq(2b);
// hcol = 32*hR + 4*o + hq; pointwise b = b0 + ks. W in REGISTERS.
// h exchange: per-thread DSMEM scatter of h_cur to all 8 peers' smem
// (double-buffered), release-flag per producer, local-smem flag polls.
__global__ __launch_bounds__(256, 1) __cluster_dims__(8, 1, 1)
void k_rec(const float* __restrict__ h0,
           const float* __restrict__ c0,
           const float* __restrict__ W,
           float* __restrict__ out) {
    __shared__ __align__(16) float    h_s[2 * HS_BUF];   // 16640 B
    __shared__ __align__(16) unsigned flags[16];         // [buf][producer]

    int bid   = blockIdx.x;
    int cid   = bid >> 3;               // cluster id 0..15
    int l     = cid >> 3;               // layer
    int bR    = cid & 7;                // b-octet
    uint32_t hR;
    asm("mov.u32 %0, %%cluster_ctarank;" : "=r"(hR));    // 0..7
    int b0    = bR << 3;
    int tid   = threadIdx.x;
    int o     = tid >> 5;               // warp
    int lane  = tid & 31;
    int ks    = lane >> 2;              // 0..7 (32-k slice / b' index)
    int hq    = lane & 3;
    int hcol  = (int)(hR << 5) + (o << 2) + hq;          // global hidden idx
    int b_pw  = b0 + ks;

    // ---- W slice -> registers ----
    unsigned long long wfi[32], wgo[32];
    {
        const float* Whl = W + (size_t)l * 512 * 1024 + (size_t)256 * 1024;
#pragma unroll
        for (int kk = 0; kk < 32; kk++) {
            const float* wr = Whl + (size_t)((ks << 5) + kk) * 1024 + hcol;
            wfi[kk] = pack2(wr[0], wr[256]);     // (f, i)
            wgo[kk] = pack2(wr[512], wr[768]);   // (g, o)
        }
    }

    // remote addresses: my element offset in every peer's h_s, + flag slots
    uint32_t hs_loc = smem_u32(h_s);
    uint32_t fl_loc = smem_u32(flags);
    int myoff = (int)(hR * HS_SL) + ((o << 2) + hq) * 8 + ks;   // floats
    uint32_t datadst[8];
#pragma unroll
    for (int rk = 0; rk < 8; rk++)
        datadst[rk] = mapa_rank(hs_loc, rk) + ((uint32_t)myoff << 2);
    uint32_t flagdst = 0;
    if (tid < 8) flagdst = mapa_rank(fl_loc, tid) + (hR << 2);

    // init flags, stage h0 (buffer 0), load c
    if (tid < 16) flags[tid] = 0u;
    const float* h0l = h0 + l * BATCH * HID;
    for (int i = tid; i < 2048; i += 256) {
        int j  = i >> 3;
        int bp = i & 7;
        h_s[(j >> 5) * HS_SL + (j & 31) * 8 + bp] = h0l[(b0 + bp) * 256 + j];
    }
    float c = c0[l * BATCH * HID + b_pw * 256 + hcol];
    float h_cur = 0.0f;
    __syncthreads();
    asm volatile("barrier.cluster.arrive.aligned;" ::: "memory");
    asm volatile("barrier.cluster.wait.aligned;" ::: "memory");

    for (int t = 0; t < T_STEPS; t++) {
        int rb = t & 1;
        // prefetch pre-activations (independent of flag wait)
        size_t prow = ((size_t)l * MROWS + (size_t)t * BATCH + b_pw) * 1024 + hcol;
        float pf = __ldcs(&g_pre[prow]);
        float pi = __ldcs(&g_pre[prow + 256]);
        float pg = __ldcs(&g_pre[prow + 512]);
        float po = __ldcs(&g_pre[prow + 768]);

        // wait for my k-slice's producer (local smem flag; lane-divergent)
        if (t > 0) {
            uint32_t fladdr = fl_loc + ((rb << 3) + ks) * 4;
            unsigned v;
            do {
                asm volatile("ld.acquire.cluster.shared::cta.u32 %0, [%1];"
                             : "=r"(v) : "r"(fladdr));
            } while (v < (unsigned)t);
        }

        const float* hp = h_s + rb * HS_BUF + ks * HS_SL;

        // 8b partial dot over this thread's 32-k slice; W from registers
        unsigned long long fi[8], go[8];
#pragma unroll
        for (int i = 0; i < 8; i++) { fi[i] = 0ULL; go[i] = 0ULL; }
#pragma unroll
        for (int kk = 0; kk < 32; kk++) {
            float4 hv0 = *(const float4*)&hp[kk << 3];
            float4 hv1 = *(const float4*)&hp[(kk << 3) + 4];
            float hh[8] = {hv0.x, hv0.y, hv0.z, hv0.w,
                           hv1.x, hv1.y, hv1.z, hv1.w};
#pragma unroll
            for (int bi = 0; bi < 8; bi++) {
                unsigned long long a2 = pack2(hh[bi], hh[bi]);
                fma2(fi[bi], a2, wfi[kk]);
                fma2(go[bi], a2, wgo[kk]);
            }
        }

        // reduce-scatter over ks (lane strides 16,8,4): lane ends with bi=ks
#pragma unroll
        for (int rd = 0; rd < 3; rd++) {
            int stride = 16 >> rd;
            int half   = 4 >> rd;
            bool hi = (lane & stride) != 0;
#pragma unroll
            for (int i = 0; i < 4; i++) {
                if (i < half) {
                    unsigned long long sf = hi ? fi[i] : fi[i + half];
                    unsigned long long kf = hi ? fi[i + half] : fi[i];
                    fi[i] = add2(kf, __shfl_xor_sync(0xFFFFFFFFu, sf, stride));
                    unsigned long long sg = hi ? go[i] : go[i + half];
                    unsigned long long kg = hi ? go[i + half] : go[i];
                    go[i] = add2(kg, __shfl_xor_sync(0xFFFFFFFFu, sg, stride));
                }
            }
        }

        // pointwise — MUFU activations
        float af, ai_, ag, ao;
        unpack2(fi[0], af, ai_);
        unpack2(go[0], ag, ao);
        float gf  = fast_sigmoid(af + pf);
        float gi  = fast_sigmoid(ai_ + pi);
        float gg  = fast_tanh(ag + pg);
        float go_ = fast_sigmoid(ao + po);
        c     = gf * c + gi * gg;
        h_cur = go_ * fast_tanh(c);

        if (l == 1)
            __stcs(&out[(size_t)t * BATCH * HID + b_pw * 256 + hcol], h_cur);

        if (t == T_STEPS - 1) break;

        // DSMEM scatter: my h value into buffer (1-rb) of all 8 peers
        uint32_t boff = (uint32_t)((1 - rb) * HS_BUF) << 2;
#pragma unroll
        for (int rk = 0; rk < 8; rk++) {
            asm volatile("st.shared::cluster.f32 [%0], %1;"
                         :: "r"(datadst[rk] + boff), "f"(h_cur) : "memory");
        }
        __syncthreads();          // all 256 threads' scatters issued
        if (tid < 8) {            // publish: release-flag to peer 'tid'
            asm volatile("fence.acq_rel.cluster;" ::: "memory");
            asm volatile("st.relaxed.cluster.shared::cluster.u32 [%0], %1;"
                         :: "r"(flagdst + (uint32_t)((1 - rb) << 5)),
                            "r"((unsigned)(t + 1)) : "memory");
        }
    }

    size_t OUTH = (size_t)T_STEPS * BATCH * HID;
    out[OUTH + (size_t)l * BATCH * HID + b_pw * 256 + hcol]                = h_cur;
    out[OUTH + (size_t)NLAYER * BATCH * HID + (size_t)l * BATCH * HID
        + b_pw * 256 + hcol]                                                = c;
}

// ---------------- launch ----------------------------------------------------
extern "C" void kernel_launch(void* const* d_in, const int* in_sizes, int n_in,
                              void* d_out, int out_size) {
    const float* x    = (const float*)d_in[0];
    const float* h0   = (const float*)d_in[1];
    const float* c0   = (const float*)d_in[2];
    const float* W    = (const float*)d_in[3];
    const float* bias = (const float*)d_in[4];
    float* out = (float*)d_out;

    k_pre<<<NLAYER * (MROWS / 128) * (1024 / 128), 256>>>(x, W, bias);
    k_rec<<<NLAYER * 64, 256>>>(h0, c0, W, out);
}

// round 17
// speedup vs baseline: 1.7794x; 1.7794x over previous
#include <cuda_runtime.h>
#include <cstdint>
#include <cstddef>

#define T_STEPS 2048
#define BATCH   64
#define HID     256
#define NLAYER  2
#define MROWS   (T_STEPS * BATCH)       // 131072

// h_s smem: per buffer 8 slices (32 j each) of 8 b'; slice stride 260
// floats -> dot LDS.128: quads 4*ks mod 32 distinct -> 1 phase.
#define HS_SL   260
#define HS_BUF  (8 * HS_SL)             // 2080 floats per buffer

// k_pre smem tiles (floats)
#define ASZ (32 * 132)
#define BSZ (32 * 128)

// ---------------- scratch (static device memory; no allocation APIs) -------
__device__ float    g_pre[(size_t)NLAYER * MROWS * 1024];   // 1 GiB
__device__ float    g_h2[NLAYER][2][8][256 * 8];            // [l][buf][bR][j*8+b']
__device__ unsigned g_cnt2[NLAYER * 8][32];                 // padded counters

// ---------------- packed fp32x2 helpers ------------------------------------
__device__ __forceinline__ unsigned long long pack2(float x, float y) {
    unsigned long long r;
    asm("mov.b64 %0, {%1, %2};" : "=l"(r) : "f"(x), "f"(y));
    return r;
}
__device__ __forceinline__ void unpack2(unsigned long long v, float& x, float& y) {
    asm("mov.b64 {%0, %1}, %2;" : "=f"(x), "=f"(y) : "l"(v));
}
__device__ __forceinline__ void fma2(unsigned long long& d, unsigned long long a,
                                     unsigned long long b) {
    asm("fma.rn.f32x2 %0, %1, %2, %0;" : "+l"(d) : "l"(a), "l"(b));
}
__device__ __forceinline__ unsigned long long add2(unsigned long long a,
                                                   unsigned long long b) {
    unsigned long long r;
    asm("add.rn.f32x2 %0, %1, %2;" : "=l"(r) : "l"(a), "l"(b));
    return r;
}

// MUFU-path activations
__device__ __forceinline__ float fast_sigmoid(float x) {
    float e, r;
    asm("ex2.approx.f32 %0, %1;" : "=f"(e) : "f"(-1.4426950408889634f * x));
    asm("rcp.approx.f32 %0, %1;" : "=f"(r) : "f"(1.0f + e));
    return r;
}
__device__ __forceinline__ float fast_tanh(float x) {
    float e, r;
    asm("ex2.approx.f32 %0, %1;" : "=f"(e) : "f"(2.8853900817779268f * x));
    asm("rcp.approx.f32 %0, %1;" : "=f"(r) : "f"(1.0f + e));
    return 1.0f - 2.0f * r;
}

__device__ __forceinline__ uint32_t smem_u32(const void* p) {
    uint32_t a;
    asm("{ .reg .u64 t; cvta.to.shared.u64 t, %1; cvt.u32.u64 %0, t; }"
        : "=r"(a) : "l"(p));
    return a;
}

// ---------------- kernel 1: pre[l,t,b,:] = x[t,b,:] @ Wx[l] + b[l] ---------
// Software-pipelined: A tile LDG->regs->STS, B tile cp.async, double-buffered
// smem, ONE syncthreads per k-chunk.
__global__ __launch_bounds__(256, 2) void k_pre(const float* __restrict__ x,
                                                const float* __restrict__ W,
                                                const float* __restrict__ bias) {
    extern __shared__ __align__(16) float sm[];
    // layout: As[2][ASZ], Bs[2][BSZ]
    float* Bs_base = sm + 2 * ASZ;

    if (blockIdx.x == 0 && threadIdx.x < NLAYER * 8)
        g_cnt2[threadIdx.x][0] = 0u;

    int bid  = blockIdx.x;
    int l    = bid >> 13;
    int rem  = bid & 8191;
    int mt   = rem >> 3;
    int nt   = rem & 7;
    int row0 = mt << 7;
    int col0 = nt << 7;
    int tid  = threadIdx.x;
    int tm   = tid >> 4;
    int tn   = tid & 15;

    const float* Wl = W + (size_t)l * 512 * 1024;

    // per-thread load indices
    int am[4], ak4[4], bkk[4], bn4[4];
#pragma unroll
    for (int i = 0; i < 4; i++) {
        int aidx = tid + i * 256;
        am[i]  = aidx >> 3;
        ak4[i] = (aidx & 7) << 2;
        bkk[i] = (tid >> 5) + i * 8;
        bn4[i] = (tid & 31) << 2;
    }
    uint32_t bs_u32 = smem_u32(Bs_base);

    unsigned long long acc[8][4];
#pragma unroll
    for (int i = 0; i < 8; i++)
#pragma unroll
        for (int j = 0; j < 4; j++) acc[i][j] = 0ULL;

    float4 av[4];
    // prologue: A(0) -> regs, B(0) -> cp.async into buf 0
#pragma unroll
    for (int i = 0; i < 4; i++)
        av[i] = *(const float4*)&x[(size_t)(row0 + am[i]) * 256 + ak4[i]];
#pragma unroll
    for (int i = 0; i < 4; i++) {
        uint32_t d = bs_u32 + (uint32_t)((bkk[i] * 128 + bn4[i]) << 2);
        const float* g = &Wl[(size_t)bkk[i] * 1024 + col0 + bn4[i]];
        asm volatile("cp.async.ca.shared.global [%0], [%1], 16;"
                     :: "r"(d), "l"(g));
    }
    asm volatile("cp.async.commit_group;");

#pragma unroll
    for (int c = 0; c < 8; c++) {
        int cur = c & 1;
        float* Asc = sm + cur * ASZ;
        float* Bsc = Bs_base + cur * BSZ;

        // STS A(c) from regs (transpose scatter)
#pragma unroll
        for (int i = 0; i < 4; i++) {
            Asc[(ak4[i] + 0) * 132 + am[i]] = av[i].x;
            Asc[(ak4[i] + 1) * 132 + am[i]] = av[i].y;
            Asc[(ak4[i] + 2) * 132 + am[i]] = av[i].z;
            Asc[(ak4[i] + 3) * 132 + am[i]] = av[i].w;
        }
        asm volatile("cp.async.wait_group 0;");
        __syncthreads();

        if (c < 7) {
            int kc = (c + 1) << 5;
#pragma unroll
            for (int i = 0; i < 4; i++)
                av[i] = *(const float4*)&x[(size_t)(row0 + am[i]) * 256 + kc + ak4[i]];
            uint32_t bdst = bs_u32 + (uint32_t)(((1 - cur) * BSZ) << 2);
#pragma unroll
            for (int i = 0; i < 4; i++) {
                uint32_t d = bdst + (uint32_t)((bkk[i] * 128 + bn4[i]) << 2);
                const float* g = &Wl[(size_t)(kc + bkk[i]) * 1024 + col0 + bn4[i]];
                asm volatile("cp.async.ca.shared.global [%0], [%1], 16;"
                             :: "r"(d), "l"(g));
            }
            asm volatile("cp.async.commit_group;");
        }

#pragma unroll
        for (int k = 0; k < 32; k++) {
            float4 a0 = *(const float4*)&Asc[k * 132 + tm * 8];
            float4 a1 = *(const float4*)&Asc[k * 132 + tm * 8 + 4];
            ulonglong2 bb01 = *(const ulonglong2*)&Bsc[k * 128 + tn * 8];
            ulonglong2 bb23 = *(const ulonglong2*)&Bsc[k * 128 + tn * 8 + 4];
            float avv[8] = {a0.x, a0.y, a0.z, a0.w, a1.x, a1.y, a1.z, a1.w};
#pragma unroll
            for (int i = 0; i < 8; i++) {
                unsigned long long a2 = pack2(avv[i], avv[i]);
                fma2(acc[i][0], a2, bb01.x);
                fma2(acc[i][1], a2, bb01.y);
                fma2(acc[i][2], a2, bb23.x);
                fma2(acc[i][3], a2, bb23.y);
            }
        }
    }

    float bv[8];
#pragma unroll
    for (int j = 0; j < 8; j++) bv[j] = bias[l * 1024 + col0 + tn * 8 + j];
#pragma unroll
    for (int i = 0; i < 8; i++) {
        float o[8];
#pragma unroll
        for (int j = 0; j < 4; j++) unpack2(acc[i][j], o[2 * j], o[2 * j + 1]);
#pragma unroll
        for (int j = 0; j < 8; j++) o[j] += bv[j];
        size_t base = ((size_t)l * MROWS + row0 + tm * 8 + i) * 1024 + col0 + tn * 8;
        __stcs((float4*)&g_pre[base],     make_float4(o[0], o[1], o[2], o[3]));
        __stcs((float4*)&g_pre[base + 4], make_float4(o[4], o[5], o[6], o[7]));
    }
}

// ---------------- kernel 2: persistent recurrence ---------------------------
// 128 CTAs = 2 layers x 8 b-octets (8 b) x 8 hcol-groups (32 hcols).
// Group barrier = central counter (8 arrivals). ALL warps poll; warp o then
// copies producer o's 1 KB chunk into the double-buffered h_s and publishes
// a local smem flag. The next dot waits on local flags only.
__global__ __launch_bounds__(256, 1) void k_rec(const float* __restrict__ h0,
                                                const float* __restrict__ c0,
                                                const float* __restrict__ W,
                                                float* __restrict__ out) {
    __shared__ __align__(16) float    h_s[2 * HS_BUF];   // 16640 B
    __shared__ __align__(16) unsigned sflag[8];

    int bid   = blockIdx.x;
    int l     = bid >> 6;
    int r     = bid & 63;
    int bR    = r >> 3;                 // b-octet 0..7
    int hR    = r & 7;                  // hcol-group 0..7
    int b0    = bR << 3;
    int hcol0 = hR << 5;
    int tid   = threadIdx.x;
    int o     = tid >> 5;               // warp
    int lane  = tid & 31;
    int ks    = lane >> 2;              // 0..7 (32-k slice)
    int hq    = lane & 3;
    int hcol  = hcol0 + (o << 2) + hq;  // global hidden index
    int b_pw  = b0 + ks;                // this lane's pointwise batch row
    unsigned* cnt = &g_cnt2[l * 8 + bR][0];
    uint32_t fl_base = smem_u32(sflag);
    uint32_t fladdr  = fl_base + ((uint32_t)ks << 2);

    // ---- W slice -> registers (persistent across all 2048 steps) ----
    unsigned long long wfi[32], wgo[32];
    {
        const float* Whl = W + (size_t)l * 512 * 1024 + (size_t)256 * 1024;
#pragma unroll
        for (int kk = 0; kk < 32; kk++) {
            const float* wr = Whl + (size_t)((ks << 5) + kk) * 1024 + hcol;
            wfi[kk] = pack2(wr[0], wr[256]);     // (f, i)
            wgo[kk] = pack2(wr[512], wr[768]);   // (g, o)
        }
    }

    // init flags, stage h0 into buffer 0, load c
    if (tid < 8) sflag[tid] = 0u;
    const float* h0l = h0 + l * BATCH * HID;
    for (int i = tid; i < 2048; i += 256) {
        int j  = i >> 3;
        int bp = i & 7;
        h_s[(j >> 5) * HS_SL + (j & 31) * 8 + bp] = h0l[(b0 + bp) * 256 + j];
    }
    float c = c0[l * BATCH * HID + b_pw * 256 + hcol];
    float h_cur = 0.0f;
    __syncthreads();

    for (int t = 0; t < T_STEPS; t++) {
        int rb = t & 1;
        int wb = 1 - rb;

        // prefetch pre-activations (independent of flag wait)
        size_t prow = ((size_t)l * MROWS + (size_t)t * BATCH + b_pw) * 1024 + hcol;
        float pf = __ldcs(&g_pre[prow]);
        float pi = __ldcs(&g_pre[prow + 256]);
        float pg = __ldcs(&g_pre[prow + 512]);
        float po = __ldcs(&g_pre[prow + 768]);

        // wait for my k-slice chunk in buffer rb (local smem flag)
        {
            unsigned fv;
            do {
                asm volatile("ld.acquire.cta.shared.u32 %0, [%1];"
                             : "=r"(fv) : "r"(fladdr));
            } while (fv < (unsigned)t);
        }
        const float* hp = h_s + rb * HS_BUF + ks * HS_SL;

        // 8b partial dot over this thread's 32-k slice; W from registers
        unsigned long long fi[8], go[8];
#pragma unroll
        for (int i = 0; i < 8; i++) { fi[i] = 0ULL; go[i] = 0ULL; }
#pragma unroll
        for (int kk = 0; kk < 32; kk++) {
            float4 hv0 = *(const float4*)&hp[kk << 3];
            float4 hv1 = *(const float4*)&hp[(kk << 3) + 4];
            float hh[8] = {hv0.x, hv0.y, hv0.z, hv0.w,
                           hv1.x, hv1.y, hv1.z, hv1.w};
#pragma unroll
            for (int bi = 0; bi < 8; bi++) {
                unsigned long long a2 = pack2(hh[bi], hh[bi]);
                fma2(fi[bi], a2, wfi[kk]);
                fma2(go[bi], a2, wgo[kk]);
            }
        }

        // reduce-scatter over ks (lane strides 16,8,4): lane ends with bi=ks
#pragma unroll
        for (int rd = 0; rd < 3; rd++) {
            int stride = 16 >> rd;
            int half   = 4 >> rd;
            bool hi = (lane & stride) != 0;
#pragma unroll
            for (int i = 0; i < 4; i++) {
                if (i < half) {
                    unsigned long long sf = hi ? fi[i] : fi[i + half];
                    unsigned long long kf = hi ? fi[i + half] : fi[i];
                    fi[i] = add2(kf, __shfl_xor_sync(0xFFFFFFFFu, sf, stride));
                    unsigned long long sg = hi ? go[i] : go[i + half];
                    unsigned long long kg = hi ? go[i + half] : go[i];
                    go[i] = add2(kg, __shfl_xor_sync(0xFFFFFFFFu, sg, stride));
                }
            }
        }

        // pointwise — MUFU activations
        float af, ai_, ag, ao;
        unpack2(fi[0], af, ai_);
        unpack2(go[0], ag, ao);
        float gf  = fast_sigmoid(af + pf);
        float gi  = fast_sigmoid(ai_ + pi);
        float gg  = fast_tanh(ag + pg);
        float go_ = fast_sigmoid(ao + po);
        c     = gf * c + gi * gg;
        h_cur = go_ * fast_tanh(c);

        g_h2[l][wb][bR][hcol * 8 + ks] = h_cur;     // [j][b'] slice
        if (l == 1)
            __stcs(&out[(size_t)t * BATCH * HID + b_pw * 256 + hcol], h_cur);

        if (t == T_STEPS - 1) break;

        __syncthreads();                 // all CTA stores issued
        if (tid == 0) {
            asm volatile("red.release.gpu.global.add.u32 [%0], %1;"
                         :: "l"(cnt), "r"(1u) : "memory");
        }
        // all warps poll the group counter (coalesced same-address load)
        {
            unsigned target = 8u * (unsigned)(t + 1);
            unsigned v;
            do {
                asm volatile("ld.acquire.gpu.global.u32 %0, [%1];"
                             : "=r"(v) : "l"(cnt) : "memory");
            } while (v < target);
        }
        // warp o copies producer o's chunk (j in [32o, 32o+32)) into buf wb
        {
            const float4* src = (const float4*)g_h2[l][wb][bR];
#pragma unroll
            for (int q = 0; q < 2; q++) {
                int m  = (o << 6) + lane + (q << 5);   // float4 index
                int j  = m >> 1;
                int hf = (m & 1) << 2;
                float4 v4 = __ldcg(&src[m]);
                *(float4*)&h_s[wb * HS_BUF + (j >> 5) * HS_SL
                               + (j & 31) * 8 + hf] = v4;
            }
            __syncwarp();
            if (lane == 0) {
                asm volatile("st.release.cta.shared.u32 [%0], %1;"
                             :: "r"(fl_base + ((uint32_t)o << 2)),
                                "r"((unsigned)(t + 1)) : "memory");
            }
        }
    }

    size_t OUTH = (size_t)T_STEPS * BATCH * HID;
    out[OUTH + (size_t)l * BATCH * HID + b_pw * 256 + hcol]                = h_cur;
    out[OUTH + (size_t)NLAYER * BATCH * HID + (size_t)l * BATCH * HID
        + b_pw * 256 + hcol]                                                = c;
}

// ---------------- launch ----------------------------------------------------
extern "C" void kernel_launch(void* const* d_in, const int* in_sizes, int n_in,
                              void* d_out, int out_size) {
    const float* x    = (const float*)d_in[0];
    const float* h0   = (const float*)d_in[1];
    const float* c0   = (const float*)d_in[2];
    const float* W    = (const float*)d_in[3];
    const float* bias = (const float*)d_in[4];
    float* out = (float*)d_out;

    size_t pre_smem = (size_t)(2 * ASZ + 2 * BSZ) * sizeof(float);   // 66,560 B
    cudaFuncSetAttribute(k_pre, cudaFuncAttributeMaxDynamicSharedMemorySize,
                         (int)pre_smem);

    k_pre<<<NLAYER * (MROWS / 128) * (1024 / 128), 256, pre_smem>>>(x, W, bias);
    k_rec<<<NLAYER * 64, 256>>>(h0, c0, W, out);
}